// round 6
// baseline (speedup 1.0000x reference)
#include <cuda_runtime.h>
#include <math.h>

#define NB    128
#define NTH   512
#define BB    64
#define TT    512
#define IND   512
#define XD    1024
#define OUTD  256

#define WS_STRIDE  68
#define WS_PHASE   (128 * WS_STRIDE)          // 8704 floats per weight tile
#define AS2_STRIDE 130
#define SMEM_FLOATS (4 * WS_PHASE + 128 * AS2_STRIDE)   // 34816 + 16640 = 51456
#define SMEM_BYTES  (SMEM_FLOATS * 4)                   // 205824

typedef unsigned long long ull;

// packed f32x2 FMA (sm_100+): per-lane IEEE fma.rn, 2 MACs per instruction
#define FMA2(c, a, b) asm("fma.rn.f32x2 %0, %1, %2, %0;" : "+l"(c) : "l"(a), "l"(b))
#define UNPK(c, lo, hi) asm("mov.b64 {%0, %1}, %2;" : "=f"(lo), "=f"(hi) : "l"(c))

// ------------------------- device scratch ---------------------------------
__device__ float g_actin[(size_t)BB * TT * XD];   // [t*64+b][XD]
__device__ float g_P[(size_t)BB * TT * XD];       // [t*64+b][XD]
__device__ float g_h3all[(size_t)TT * BB * XD];   // [t][b][XD]
__device__ float g_h1[BB * XD];
__device__ float g_h2[BB * XD];
__device__ float g_rs[BB * XD];
__device__ float g_normpart[BB][16];              // [row][tile] partial sumsq of rs
__device__ float g_part[64 * 8 * 4096];           // (phase*16+tile, sp) partial slabs
__device__ unsigned g_cnt[64];                    // per (phase,tile) arrival counters
__device__ unsigned g_flag[4][16 * 32];           // epoch flags, 128B apart
__device__ unsigned g_barcnt;
__device__ unsigned g_bargen;

// ------------------------- activation (matches reference) -----------------
__device__ __forceinline__ float rand_act(float v, int idx, float mx) {
    float r;
    switch (idx) {
    case 0:  r = fmaxf(v, 0.0f); break;
    case 1:  r = 1.0f / (1.0f + expf(-v)); break;
    case 2:  r = tanhf(v); break;
    case 3:  r = (v >= 0.0f) ? v : 0.1f * v; break;
    default: {
        const float a = 1.6732632423543772f, s = 1.0507009873554805f;
        r = (v > 0.0f) ? s * v : s * a * expm1f(v);
    } break;
    }
    return fminf(r, mx);
}

__device__ __forceinline__ float4 act4(float4 v, int4 id, float4 mx) {
    return make_float4(rand_act(v.x, id.x, mx.x), rand_act(v.y, id.y, mx.y),
                       rand_act(v.z, id.z, mx.z), rand_act(v.w, id.w, mx.w));
}

// ------------------------- grid-wide barrier (4 uses total) ----------------
__device__ __forceinline__ void gsync(unsigned& mygen) {
    __threadfence();
    __syncthreads();
    if (threadIdx.x == 0) {
        unsigned old = atomicAdd(&g_barcnt, 1u);
        if (old == NB - 1u) {
            g_barcnt = 0u;
            __threadfence();
            atomicAdd(&g_bargen, 1u);
        } else {
            while (((volatile unsigned*)&g_bargen)[0] == mygen) { __nanosleep(64); }
        }
    }
    __syncthreads();
    mygen += 1u;
}

// ------------------------- dataflow wait: tight spin, NO nanosleep ---------
__device__ __forceinline__ void wait2(volatile unsigned* f, int a, int b, unsigned tgt) {
    if (threadIdx.x < 2) {
        const int i = threadIdx.x ? b : a;
        while (f[i * 32] < tgt) {}
    }
    __syncthreads();
}

__device__ __forceinline__ void publish(volatile unsigned* f, unsigned v) {
    __threadfence();
    __syncthreads();
    if (threadIdx.x == 0) *f = v;
}

// ------------------------- shared staging ----------------------------------
// A (64 rows x 128 k) -> As2[k][2*row] with each value DUPLICATED (f32x2 splat-free)
__device__ __forceinline__ void stageA_dup(const float* __restrict__ A, int lda, float* As2) {
    const int row = threadIdx.x >> 3;
    const int f4  = threadIdx.x & 7;
    const float4* src = (const float4*)(A + (size_t)row * lda);
#pragma unroll
    for (int j = 0; j < 4; j++) {
        float4 v = __ldcg(&src[f4 + 8 * j]);
        const int k = (f4 + 8 * j) << 2;
        *(float2*)(As2 + (size_t)(k + 0) * AS2_STRIDE + 2 * row) = make_float2(v.x, v.x);
        *(float2*)(As2 + (size_t)(k + 1) * AS2_STRIDE + 2 * row) = make_float2(v.y, v.y);
        *(float2*)(As2 + (size_t)(k + 2) * AS2_STRIDE + 2 * row) = make_float2(v.z, v.z);
        *(float2*)(As2 + (size_t)(k + 3) * AS2_STRIDE + 2 * row) = make_float2(v.w, v.w);
    }
}

// B (64 rows x 128 k, row-major, constant) -> Bs[k][row], stride 68
__device__ __forceinline__ void stageB_T(const float* __restrict__ B, int ldb, float* Bs) {
    const int row = threadIdx.x >> 3;
    const int f4  = threadIdx.x & 7;
    const float4* src = (const float4*)(B + (size_t)row * ldb);
#pragma unroll
    for (int j = 0; j < 4; j++) {
        float4 v = __ldg(&src[f4 + 8 * j]);
        const int k = (f4 + 8 * j) << 2;
        Bs[(size_t)(k + 0) * WS_STRIDE + row] = v.x;
        Bs[(size_t)(k + 1) * WS_STRIDE + row] = v.y;
        Bs[(size_t)(k + 2) * WS_STRIDE + row] = v.z;
        Bs[(size_t)(k + 3) * WS_STRIDE + row] = v.w;
    }
}

// ------------------------- packed-f32x2 inner GEMM (K=128, shared-only) ----
__device__ __forceinline__ void gemm_sh(const float* As2, const float* Bsh,
                                        ull& c00, ull& c01, ull& c10, ull& c11,
                                        int tx, int ty) {
    const float* ap = As2 + (ty << 2);   // (a0,a0) at +0, (a1,a1) at +2
    const float* bp = Bsh + (tx << 2);   // (b0,b1) at +0, (b2,b3) at +2
#pragma unroll 8
    for (int k = 0; k < 128; k++) {
        ull a0 = *(const ull*)(ap + (size_t)k * AS2_STRIDE);
        ull a1 = *(const ull*)(ap + (size_t)k * AS2_STRIDE + 2);
        ull b0 = *(const ull*)(bp + (size_t)k * WS_STRIDE);
        ull b1 = *(const ull*)(bp + (size_t)k * WS_STRIDE + 2);
        FMA2(c00, a0, b0); FMA2(c01, a0, b1);
        FMA2(c10, a1, b0); FMA2(c11, a1, b1);
    }
}

__device__ __forceinline__ void unpack_acc(ull c00, ull c01, ull c10, ull c11,
                                           float acc[2][4]) {
    UNPK(c00, acc[0][0], acc[0][1]); UNPK(c01, acc[0][2], acc[0][3]);
    UNPK(c10, acc[1][0], acc[1][1]); UNPK(c11, acc[1][2], acc[1][3]);
}

// ------------------------- chunked full-K task GEMM (precompute/output) ----
__device__ __forceinline__ void gemm_task(const float* A, int lda,
                                          const float* B, int ldb,
                                          int nchunk, float acc[2][4],
                                          float* As2, float* Bs, int tx, int ty) {
    ull c00 = 0, c01 = 0, c10 = 0, c11 = 0;
    for (int c = 0; c < nchunk; c++) {
        stageA_dup(A + (c << 7), lda, As2);
        stageB_T(B + (c << 7), ldb, Bs);
        __syncthreads();
        gemm_sh(As2, Bs, c00, c01, c10, c11, tx, ty);
        __syncthreads();
    }
    unpack_acc(c00, c01, c10, c11, acc);
}

// ------------------------- k-split finish ----------------------------------
__device__ __forceinline__ bool ksplit(int slot, int sp, float acc[2][4], int tx, int ty) {
    float* slab = &g_part[((size_t)slot * 8 + sp) * 4096];
#pragma unroll
    for (int i = 0; i < 2; i++) {
        float4 v = make_float4(acc[i][0], acc[i][1], acc[i][2], acc[i][3]);
        __stcg((float4*)&slab[((ty << 1) + i) * 64 + (tx << 2)], v);
    }
    __threadfence();
    __syncthreads();
    __shared__ int s_last;
    if (threadIdx.x == 0) {
        unsigned old = atomicAdd(&g_cnt[slot], 1u);
        s_last = (old == 7u);
        if (old == 7u) g_cnt[slot] = 0u;
    }
    __syncthreads();
    if (!s_last) return false;
    __threadfence();
#pragma unroll
    for (int s = 0; s < 8; s++) {
        if (s == sp) continue;
        const float* os = &g_part[((size_t)slot * 8 + s) * 4096];
#pragma unroll
        for (int i = 0; i < 2; i++) {
            float4 pv = __ldcg((const float4*)&os[((ty << 1) + i) * 64 + (tx << 2)]);
            acc[i][0] += pv.x; acc[i][1] += pv.y; acc[i][2] += pv.z; acc[i][3] += pv.w;
        }
    }
    return true;
}

// ------------------------- main persistent kernel --------------------------
__global__ void __launch_bounds__(NTH, 1)
bnn_kernel(const float* __restrict__ x,
           const float* __restrict__ Wi,  const float* __restrict__ bi,
           const float* __restrict__ Wh1, const float* __restrict__ bh1,
           const float* __restrict__ Wh2, const float* __restrict__ bh2,
           const float* __restrict__ Wh3, const float* __restrict__ bh3,
           const float* __restrict__ Wo,  const float* __restrict__ bo,
           const float* __restrict__ Wr,  const float* __restrict__ br,
           const float* __restrict__ max_in,  const float* __restrict__ max_h1,
           const float* __restrict__ max_h2,  const float* __restrict__ max_h3,
           const float* __restrict__ max_out, const float* __restrict__ max_rec,
           const int* __restrict__ idx_in,  const int* __restrict__ idx_h1,
           const int* __restrict__ idx_h2,  const int* __restrict__ idx_h3,
           const int* __restrict__ idx_out, const int* __restrict__ idx_rec,
           float* __restrict__ out) {
    extern __shared__ float smem[];
    float* ws  = smem;                    // 4 persistent weight tiles (loop) / Bs scratch (pre)
    float* as2 = smem + 4 * WS_PHASE;     // duplicated-transposed A tile

    const int bid = blockIdx.x;
    const int tid = threadIdx.x;
    const int tx  = tid & 15;          // output col group (4 cols)
    const int ty  = tid >> 4;          // output row group (2 rows), 0..31

    unsigned mygen = ((volatile unsigned*)&g_bargen)[0];

    // ---- init state (every launch) ----
    {
        int i = bid * NTH + tid;           // exactly BB*XD threads
        g_rs[i] = 0.0f;
        if (bid == 0) {
            for (int j = tid; j < BB * 16; j += NTH) ((float*)g_normpart)[j] = 0.0f;
            for (int j = tid; j < 4 * 16 * 32; j += NTH) ((unsigned*)g_flag)[j] = 0u;
            if (tid < 64) g_cnt[tid] = 0u;
        }
    }
    gsync(mygen);

    // ================= Phase A: actin = act(x @ Wi^T + bi), permuted =======
    for (int task = bid; task < 512 * 16; task += NB) {
        const int rt = task >> 4, nt = task & 15;
        float acc[2][4];
        gemm_task(x + (size_t)rt * 64 * IND, IND,
                  Wi + (size_t)(nt << 6) * IND, IND, 4, acc, as2, ws, tx, ty);
        const int col0 = (nt << 6) + (tx << 2);
        const int4   id4 = __ldg((const int4*)&idx_in[col0]);
        const float4 mx4 = __ldg((const float4*)&max_in[col0]);
        const float4 b4  = __ldg((const float4*)&bi[col0]);
#pragma unroll
        for (int i = 0; i < 2; i++) {
            const int g = rt * 64 + (ty << 1) + i;
            const int b = g >> 9, t = g & 511;
            float4 v = make_float4(acc[i][0] + b4.x, acc[i][1] + b4.y,
                                   acc[i][2] + b4.z, acc[i][3] + b4.w);
            v = act4(v, id4, mx4);
            __stcg((float4*)&g_actin[(size_t)(t * BB + b) * XD + col0], v);
        }
    }
    gsync(mygen);

    // ================= Phase B: P = actin @ Wh1a^T + bh1 ===================
    for (int task = bid; task < 512 * 16; task += NB) {
        const int rt = task >> 4, nt = task & 15;
        float acc[2][4];
        gemm_task(g_actin + (size_t)rt * 64 * XD, XD,
                  Wh1 + (size_t)(nt << 6) * (2 * XD), 2 * XD, 8, acc, as2, ws, tx, ty);
        const int col0 = (nt << 6) + (tx << 2);
        const float4 b4 = __ldg((const float4*)&bh1[col0]);
#pragma unroll
        for (int i = 0; i < 2; i++) {
            const int row = rt * 64 + (ty << 1) + i;
            float4 v = make_float4(acc[i][0] + b4.x, acc[i][1] + b4.y,
                                   acc[i][2] + b4.z, acc[i][3] + b4.w);
            __stcg((float4*)&g_P[(size_t)row * XD + col0], v);
        }
    }
    gsync(mygen);

    // ================= preload persistent loop weights into shared =========
    const int nt = bid >> 3;           // output tile 0..15
    const int sp = bid & 7;            // k-split 0..7
    const int n0 = nt << 6;
    const int k0 = sp << 7;
    const int col0 = n0 + (tx << 2);

    stageB_T(Wh1 + (size_t)n0 * (2 * XD) + XD + k0, 2 * XD, ws + 0 * WS_PHASE);
    stageB_T(Wh2 + (size_t)n0 * XD + k0,            XD,     ws + 1 * WS_PHASE);
    stageB_T(Wh3 + (size_t)n0 * XD + k0,            XD,     ws + 2 * WS_PHASE);
    stageB_T(Wr  + (size_t)n0 * XD + k0,            XD,     ws + 3 * WS_PHASE);
    __syncthreads();

    // ================= time loop (dataflow, tight-spin waits) ==============
    for (int s = 0; s < TT; s++) {
        // ---- Phase 1: h1 = act( (rs@Wh1b^T)*rinv + P[s] ) ----
        wait2(g_flag[3], 2 * sp, 2 * sp + 1, (unsigned)s);
        {
            stageA_dup(g_rs + k0, XD, as2);
            __syncthreads();
            ull c00 = 0, c01 = 0, c10 = 0, c11 = 0;
            gemm_sh(as2, ws + 0 * WS_PHASE, c00, c01, c10, c11, tx, ty);
            __syncthreads();
            float acc[2][4];
            unpack_acc(c00, c01, c10, c11, acc);
            if (ksplit(0 * 16 + nt, sp, acc, tx, ty)) {
                const int4   id4 = __ldg((const int4*)&idx_h1[col0]);
                const float4 mx4 = __ldg((const float4*)&max_h1[col0]);
                const float* Pt = g_P + (size_t)s * BB * XD;
#pragma unroll
                for (int i = 0; i < 2; i++) {
                    const int row = (ty << 1) + i;
                    float4 n0v = __ldcg((const float4*)&g_normpart[row][0]);
                    float4 n1v = __ldcg((const float4*)&g_normpart[row][4]);
                    float4 n2v = __ldcg((const float4*)&g_normpart[row][8]);
                    float4 n3v = __ldcg((const float4*)&g_normpart[row][12]);
                    float ss = ((n0v.x + n0v.y) + (n0v.z + n0v.w))
                             + ((n1v.x + n1v.y) + (n1v.z + n1v.w))
                             + ((n2v.x + n2v.y) + (n2v.z + n2v.w))
                             + ((n3v.x + n3v.y) + (n3v.z + n3v.w));
                    const float rinv = 1.0f / fmaxf(sqrtf(ss), 1e-12f);
                    const float4 p4 = __ldg((const float4*)&Pt[(size_t)row * XD + col0]);
                    float4 v = make_float4(acc[i][0] * rinv + p4.x, acc[i][1] * rinv + p4.y,
                                           acc[i][2] * rinv + p4.z, acc[i][3] * rinv + p4.w);
                    v = act4(v, id4, mx4);
                    __stcg((float4*)&g_h1[row * XD + col0], v);
                }
                publish(&g_flag[0][nt * 32], (unsigned)(s + 1));
            }
        }

        // ---- Phase 2: h2 = act(h1 @ Wh2^T + bh2) ----
        wait2(g_flag[0], 2 * sp, 2 * sp + 1, (unsigned)(s + 1));
        {
            stageA_dup(g_h1 + k0, XD, as2);
            __syncthreads();
            ull c00 = 0, c01 = 0, c10 = 0, c11 = 0;
            gemm_sh(as2, ws + 1 * WS_PHASE, c00, c01, c10, c11, tx, ty);
            __syncthreads();
            float acc[2][4];
            unpack_acc(c00, c01, c10, c11, acc);
            if (ksplit(1 * 16 + nt, sp, acc, tx, ty)) {
                const int4   id4 = __ldg((const int4*)&idx_h2[col0]);
                const float4 mx4 = __ldg((const float4*)&max_h2[col0]);
                const float4 b4  = __ldg((const float4*)&bh2[col0]);
#pragma unroll
                for (int i = 0; i < 2; i++) {
                    const int row = (ty << 1) + i;
                    float4 v = make_float4(acc[i][0] + b4.x, acc[i][1] + b4.y,
                                           acc[i][2] + b4.z, acc[i][3] + b4.w);
                    v = act4(v, id4, mx4);
                    __stcg((float4*)&g_h2[row * XD + col0], v);
                }
                publish(&g_flag[1][nt * 32], (unsigned)(s + 1));
            }
        }

        // ---- Phase 3: h3all[s] = act(h2 @ Wh3^T + bh3) ----
        wait2(g_flag[1], 2 * sp, 2 * sp + 1, (unsigned)(s + 1));
        {
            stageA_dup(g_h2 + k0, XD, as2);
            __syncthreads();
            ull c00 = 0, c01 = 0, c10 = 0, c11 = 0;
            gemm_sh(as2, ws + 2 * WS_PHASE, c00, c01, c10, c11, tx, ty);
            __syncthreads();
            float acc[2][4];
            unpack_acc(c00, c01, c10, c11, acc);
            if (ksplit(2 * 16 + nt, sp, acc, tx, ty)) {
                const int4   id4 = __ldg((const int4*)&idx_h3[col0]);
                const float4 mx4 = __ldg((const float4*)&max_h3[col0]);
                const float4 b4  = __ldg((const float4*)&bh3[col0]);
                float* h3t = g_h3all + (size_t)s * BB * XD;
#pragma unroll
                for (int i = 0; i < 2; i++) {
                    const int row = (ty << 1) + i;
                    float4 v = make_float4(acc[i][0] + b4.x, acc[i][1] + b4.y,
                                           acc[i][2] + b4.z, acc[i][3] + b4.w);
                    v = act4(v, id4, mx4);
                    __stcg((float4*)&h3t[row * XD + col0], v);
                }
                publish(&g_flag[2][nt * 32], (unsigned)(s + 1));
            }
        }

        // ---- Phase 4: rs = act(h3 @ Wr^T + br) + norm partials ----
        wait2(g_flag[2], 2 * sp, 2 * sp + 1, (unsigned)(s + 1));
        {
            stageA_dup(g_h3all + (size_t)s * BB * XD + k0, XD, as2);
            __syncthreads();
            ull c00 = 0, c01 = 0, c10 = 0, c11 = 0;
            gemm_sh(as2, ws + 3 * WS_PHASE, c00, c01, c10, c11, tx, ty);
            __syncthreads();
            float acc[2][4];
            unpack_acc(c00, c01, c10, c11, acc);
            if (ksplit(3 * 16 + nt, sp, acc, tx, ty)) {
                const int4   id4 = __ldg((const int4*)&idx_rec[col0]);
                const float4 mx4 = __ldg((const float4*)&max_rec[col0]);
                const float4 b4  = __ldg((const float4*)&br[col0]);
#pragma unroll
                for (int i = 0; i < 2; i++) {
                    const int row = (ty << 1) + i;
                    float4 v = make_float4(acc[i][0] + b4.x, acc[i][1] + b4.y,
                                           acc[i][2] + b4.z, acc[i][3] + b4.w);
                    v = act4(v, id4, mx4);
                    __stcg((float4*)&g_rs[row * XD + col0], v);
                    float sq = v.x * v.x + v.y * v.y + v.z * v.z + v.w * v.w;
                    sq += __shfl_xor_sync(0xffffffffu, sq, 1, 16);
                    sq += __shfl_xor_sync(0xffffffffu, sq, 2, 16);
                    sq += __shfl_xor_sync(0xffffffffu, sq, 4, 16);
                    sq += __shfl_xor_sync(0xffffffffu, sq, 8, 16);
                    if (tx == 0) __stcg(&g_normpart[row][nt], sq);
                }
                publish(&g_flag[3][nt * 32], (unsigned)(s + 1));
            }
        }
    }
    gsync(mygen);

    // ================= Output GEMM: y = act(H3 @ Wo^T + bo) ================
    // (overwrites ws scratch — weights no longer needed)
    for (int task = bid; task < 512 * 4; task += NB) {
        const int t = task >> 2, ot = task & 3;
        float acc[2][4];
        gemm_task(g_h3all + (size_t)t * BB * XD, XD,
                  Wo + (size_t)(ot << 6) * XD, XD, 8, acc, as2, ws, tx, ty);
        const int oc0 = (ot << 6) + (tx << 2);
        const int4   id4 = __ldg((const int4*)&idx_out[oc0]);
        const float4 mx4 = __ldg((const float4*)&max_out[oc0]);
        const float4 b4  = __ldg((const float4*)&bo[oc0]);
#pragma unroll
        for (int i = 0; i < 2; i++) {
            const int b = (ty << 1) + i;   // batch row
            float4 v = make_float4(acc[i][0] + b4.x, acc[i][1] + b4.y,
                                   acc[i][2] + b4.z, acc[i][3] + b4.w);
            v = act4(v, id4, mx4);
            __stcg((float4*)&out[((size_t)b * TT + t) * OUTD + oc0], v);
        }
    }
}

// ------------------------- launch ------------------------------------------
extern "C" void kernel_launch(void* const* d_in, const int* in_sizes, int n_in,
                              void* d_out, int out_size) {
    const float* x       = (const float*)d_in[0];
    const float* Wi      = (const float*)d_in[1];
    const float* bi      = (const float*)d_in[2];
    const float* Wh1     = (const float*)d_in[3];
    const float* bh1     = (const float*)d_in[4];
    const float* Wh2     = (const float*)d_in[5];
    const float* bh2     = (const float*)d_in[6];
    const float* Wh3     = (const float*)d_in[7];
    const float* bh3     = (const float*)d_in[8];
    const float* Wo      = (const float*)d_in[9];
    const float* bo      = (const float*)d_in[10];
    const float* Wr      = (const float*)d_in[11];
    const float* br      = (const float*)d_in[12];
    const float* max_in  = (const float*)d_in[13];
    const float* max_h1  = (const float*)d_in[14];
    const float* max_h2  = (const float*)d_in[15];
    const float* max_h3  = (const float*)d_in[16];
    const float* max_out = (const float*)d_in[17];
    const float* max_rec = (const float*)d_in[18];
    const int*   idx_in  = (const int*)d_in[19];
    const int*   idx_h1  = (const int*)d_in[20];
    const int*   idx_h2  = (const int*)d_in[21];
    const int*   idx_h3  = (const int*)d_in[22];
    const int*   idx_out = (const int*)d_in[23];
    const int*   idx_rec = (const int*)d_in[24];

    static int configured = 0;
    if (!configured) {
        cudaFuncSetAttribute(bnn_kernel, cudaFuncAttributeMaxDynamicSharedMemorySize,
                             SMEM_BYTES);
        configured = 1;
    }

    bnn_kernel<<<NB, NTH, SMEM_BYTES>>>(x, Wi, bi, Wh1, bh1, Wh2, bh2, Wh3, bh3,
                                        Wo, bo, Wr, br,
                                        max_in, max_h1, max_h2, max_h3, max_out, max_rec,
                                        idx_in, idx_h1, idx_h2, idx_h3, idx_out, idx_rec,
                                        (float*)d_out);
}

// round 7
// speedup vs baseline: 1.0237x; 1.0237x over previous
#include <cuda_runtime.h>
#include <math.h>

#define NB    128
#define NTH   512
#define BB    64
#define TT    512
#define IND   512
#define XD    1024
#define OUTD  256

#define WS_STRIDE  68
#define WS_PHASE   (128 * WS_STRIDE)           // 8704 floats per weight tile
#define AS2_STRIDE 132                          // 528B rows: 16B aligned
#define SMEM_FLOATS (4 * WS_PHASE + 128 * AS2_STRIDE)   // 34816 + 16896 = 51712
#define SMEM_BYTES  (SMEM_FLOATS * 4)                   // 206848

typedef unsigned long long ull;

// packed f32x2 FMA (sm_100+): per-lane IEEE fma.rn, 2 MACs per instruction
#define FMA2(c, a, b) asm("fma.rn.f32x2 %0, %1, %2, %0;" : "+l"(c) : "l"(a), "l"(b))
#define UNPK(c, lo, hi) asm("mov.b64 {%0, %1}, %2;" : "=f"(lo), "=f"(hi) : "l"(c))

// ------------------------- device scratch ---------------------------------
__device__ float g_actin[(size_t)BB * TT * XD];   // [t*64+b][XD]
__device__ float g_P[(size_t)BB * TT * XD];       // [t*64+b][XD]
__device__ float g_h3all[(size_t)TT * BB * XD];   // [t][b][XD]
__device__ float g_h1[BB * XD];
__device__ float g_h2[BB * XD];
__device__ float g_rs[BB * XD];
__device__ float g_normpart[BB][16];              // [row][tile] partial sumsq of rs
__device__ float g_part[64 * 8 * 4096];           // (phase*16+tile, sp) 16KB slabs
__device__ unsigned g_scnt[64 * 8];               // slab arrival counters (monotonic), 32B apart
__device__ unsigned g_hcnt[64 * 8];               // h-ready epoch counters (monotonic), 32B apart
__device__ unsigned g_barcnt;
__device__ unsigned g_bargen;

// ------------------------- scoped atomics (no CCTL.IVALL fences) -----------
__device__ __forceinline__ unsigned atom_acqrel_add(unsigned* p) {
    unsigned o;
    asm volatile("atom.acq_rel.gpu.add.u32 %0, [%1], %2;"
                 : "=r"(o) : "l"(p), "r"(1u) : "memory");
    return o;
}
__device__ __forceinline__ void red_release_add(unsigned* p) {
    asm volatile("red.release.gpu.add.u32 [%0], %1;" :: "l"(p), "r"(1u) : "memory");
}
__device__ __forceinline__ unsigned ld_acquire(const unsigned* p) {
    unsigned v;
    asm volatile("ld.acquire.gpu.u32 %0, [%1];" : "=r"(v) : "l"(p) : "memory");
    return v;
}

// ------------------------- activation (matches reference) -----------------
__device__ __forceinline__ float rand_act(float v, int idx, float mx) {
    float r;
    switch (idx) {
    case 0:  r = fmaxf(v, 0.0f); break;
    case 1:  r = 1.0f / (1.0f + expf(-v)); break;
    case 2:  r = tanhf(v); break;
    case 3:  r = (v >= 0.0f) ? v : 0.1f * v; break;
    default: {
        const float a = 1.6732632423543772f, s = 1.0507009873554805f;
        r = (v > 0.0f) ? s * v : s * a * expm1f(v);
    } break;
    }
    return fminf(r, mx);
}

__device__ __forceinline__ float4 act4(float4 v, int4 id, float4 mx) {
    return make_float4(rand_act(v.x, id.x, mx.x), rand_act(v.y, id.y, mx.y),
                       rand_act(v.z, id.z, mx.z), rand_act(v.w, id.w, mx.w));
}

// ------------------------- grid-wide barrier (pre/post loop only) ----------
__device__ __forceinline__ void gsync(unsigned& mygen) {
    __threadfence();
    __syncthreads();
    if (threadIdx.x == 0) {
        unsigned old = atomicAdd(&g_barcnt, 1u);
        if (old == NB - 1u) {
            g_barcnt = 0u;
            __threadfence();
            atomicAdd(&g_bargen, 1u);
        } else {
            while (((volatile unsigned*)&g_bargen)[0] == mygen) { __nanosleep(64); }
        }
    }
    __syncthreads();
    mygen += 1u;
}

// ------------------------- dataflow wait: acquire poll ---------------------
__device__ __forceinline__ void waitcnt(const unsigned* c0, const unsigned* c1, unsigned tgt) {
    if (threadIdx.x < 2) {
        const unsigned* p = threadIdx.x ? c1 : c0;
        while (ld_acquire(p) < tgt) {}
    }
    __syncthreads();
}

// ------------------------- shared staging ----------------------------------
// A (64 rows x 128 k) -> As2[k][2*row] with each value DUPLICATED
__device__ __forceinline__ void stageA_dup(const float* __restrict__ A, int lda, float* As2) {
    const int row = threadIdx.x >> 3;
    const int f4  = threadIdx.x & 7;
    const float4* src = (const float4*)(A + (size_t)row * lda);
#pragma unroll
    for (int j = 0; j < 4; j++) {
        float4 v = __ldcg(&src[f4 + 8 * j]);
        const int k = (f4 + 8 * j) << 2;
        *(float2*)(As2 + (size_t)(k + 0) * AS2_STRIDE + 2 * row) = make_float2(v.x, v.x);
        *(float2*)(As2 + (size_t)(k + 1) * AS2_STRIDE + 2 * row) = make_float2(v.y, v.y);
        *(float2*)(As2 + (size_t)(k + 2) * AS2_STRIDE + 2 * row) = make_float2(v.z, v.z);
        *(float2*)(As2 + (size_t)(k + 3) * AS2_STRIDE + 2 * row) = make_float2(v.w, v.w);
    }
}

// B (64 rows x 128 k, row-major, constant) -> Bs[k][row], stride 68
__device__ __forceinline__ void stageB_T(const float* __restrict__ B, int ldb, float* Bs) {
    const int row = threadIdx.x >> 3;
    const int f4  = threadIdx.x & 7;
    const float4* src = (const float4*)(B + (size_t)row * ldb);
#pragma unroll
    for (int j = 0; j < 4; j++) {
        float4 v = __ldg(&src[f4 + 8 * j]);
        const int k = (f4 + 8 * j) << 2;
        Bs[(size_t)(k + 0) * WS_STRIDE + row] = v.x;
        Bs[(size_t)(k + 1) * WS_STRIDE + row] = v.y;
        Bs[(size_t)(k + 2) * WS_STRIDE + row] = v.z;
        Bs[(size_t)(k + 3) * WS_STRIDE + row] = v.w;
    }
}

// ------------------------- packed-f32x2 inner GEMM (K=128, LDS.128) --------
__device__ __forceinline__ void gemm_sh(const float* As2, const float* Bsh,
                                        ull& c00, ull& c01, ull& c10, ull& c11,
                                        int tx, int ty) {
    const float* ap = As2 + (ty << 2);   // (a0,a0,a1,a1) one LDS.128
    const float* bp = Bsh + (tx << 2);   // (b0,b1,b2,b3) one LDS.128
#pragma unroll 8
    for (int k = 0; k < 128; k++) {
        ulonglong2 a = *(const ulonglong2*)(ap + (size_t)k * AS2_STRIDE);
        ulonglong2 b = *(const ulonglong2*)(bp + (size_t)k * WS_STRIDE);
        FMA2(c00, a.x, b.x); FMA2(c01, a.x, b.y);
        FMA2(c10, a.y, b.x); FMA2(c11, a.y, b.y);
    }
}

__device__ __forceinline__ void unpack_acc(ull c00, ull c01, ull c10, ull c11,
                                           float acc[2][4]) {
    UNPK(c00, acc[0][0], acc[0][1]); UNPK(c01, acc[0][2], acc[0][3]);
    UNPK(c10, acc[1][0], acc[1][1]); UNPK(c11, acc[1][2], acc[1][3]);
}

// ------------------------- chunked full-K task GEMM (precompute/output) ----
__device__ __forceinline__ void gemm_task(const float* A, int lda,
                                          const float* B, int ldb,
                                          int nchunk, float acc[2][4],
                                          float* As2, float* Bs, int tx, int ty) {
    ull c00 = 0, c01 = 0, c10 = 0, c11 = 0;
    for (int c = 0; c < nchunk; c++) {
        stageA_dup(A + (c << 7), lda, As2);
        stageB_T(B + (c << 7), ldb, Bs);
        __syncthreads();
        gemm_sh(As2, Bs, c00, c01, c10, c11, tx, ty);
        __syncthreads();
    }
    unpack_acc(c00, c01, c10, c11, acc);
}

// ------------------------- k-split finish (fence-free, deterministic) ------
// Stores this block's slab; 8th arriver (acq_rel detect) re-reads ALL 8 slabs
// in fixed order (bit-deterministic sum) and returns true.
__device__ __forceinline__ bool ksplit(int slot, int sp, unsigned epoch,
                                       float acc[2][4], int tx, int ty) {
    float* slab = &g_part[((size_t)slot * 8 + sp) * 4096];
#pragma unroll
    for (int i = 0; i < 2; i++) {
        float4 v = make_float4(acc[i][0], acc[i][1], acc[i][2], acc[i][3]);
        __stcg((float4*)&slab[((ty << 1) + i) * 64 + (tx << 2)], v);
    }
    __syncthreads();                       // all slab stores done
    __shared__ unsigned s_old;
    if (threadIdx.x == 0) s_old = atom_acqrel_add(&g_scnt[slot * 8]);
    __syncthreads();
    if (s_old != 8u * epoch - 1u) return false;
    // fixed-order re-read of all 8 slabs
#pragma unroll
    for (int i = 0; i < 2; i++)
#pragma unroll
        for (int j = 0; j < 4; j++) acc[i][j] = 0.0f;
#pragma unroll
    for (int s = 0; s < 8; s++) {
        const float* os = &g_part[((size_t)slot * 8 + s) * 4096];
#pragma unroll
        for (int i = 0; i < 2; i++) {
            float4 pv = __ldcg((const float4*)&os[((ty << 1) + i) * 64 + (tx << 2)]);
            acc[i][0] += pv.x; acc[i][1] += pv.y; acc[i][2] += pv.z; acc[i][3] += pv.w;
        }
    }
    return true;
}

// publish h-ready: all epilogue stores done -> one release increment
__device__ __forceinline__ void publish_h(unsigned* c) {
    __syncthreads();
    if (threadIdx.x == 0) red_release_add(c);
}

// ------------------------- main persistent kernel --------------------------
__global__ void __launch_bounds__(NTH, 1)
bnn_kernel(const float* __restrict__ x,
           const float* __restrict__ Wi,  const float* __restrict__ bi,
           const float* __restrict__ Wh1, const float* __restrict__ bh1,
           const float* __restrict__ Wh2, const float* __restrict__ bh2,
           const float* __restrict__ Wh3, const float* __restrict__ bh3,
           const float* __restrict__ Wo,  const float* __restrict__ bo,
           const float* __restrict__ Wr,  const float* __restrict__ br,
           const float* __restrict__ max_in,  const float* __restrict__ max_h1,
           const float* __restrict__ max_h2,  const float* __restrict__ max_h3,
           const float* __restrict__ max_out, const float* __restrict__ max_rec,
           const int* __restrict__ idx_in,  const int* __restrict__ idx_h1,
           const int* __restrict__ idx_h2,  const int* __restrict__ idx_h3,
           const int* __restrict__ idx_out, const int* __restrict__ idx_rec,
           float* __restrict__ out) {
    extern __shared__ float smem[];
    float* ws  = smem;                    // 4 persistent loop weight tiles / scratch
    float* as2 = smem + 4 * WS_PHASE;     // duplicated-transposed A tile

    const int bid = blockIdx.x;
    const int tid = threadIdx.x;
    const int tx  = tid & 15;          // output col group (4 cols)
    const int ty  = tid >> 4;          // output row group (2 rows), 0..31

    unsigned mygen = ((volatile unsigned*)&g_bargen)[0];

    // ---- init state (every launch) ----
    {
        int i = bid * NTH + tid;           // exactly BB*XD threads
        g_rs[i] = 0.0f;
        if (bid == 0) {
            for (int j = tid; j < BB * 16; j += NTH) ((float*)g_normpart)[j] = 0.0f;
            if (tid < 64 * 8) { g_scnt[tid] = 0u; g_hcnt[tid] = 0u; }
        }
    }
    gsync(mygen);

    // ================= Phase A: actin = act(x @ Wi^T + bi), permuted =======
    for (int task = bid; task < 512 * 16; task += NB) {
        const int rt = task >> 4, nt = task & 15;
        float acc[2][4];
        gemm_task(x + (size_t)rt * 64 * IND, IND,
                  Wi + (size_t)(nt << 6) * IND, IND, 4, acc, as2, ws, tx, ty);
        const int col0 = (nt << 6) + (tx << 2);
        const int4   id4 = __ldg((const int4*)&idx_in[col0]);
        const float4 mx4 = __ldg((const float4*)&max_in[col0]);
        const float4 b4  = __ldg((const float4*)&bi[col0]);
#pragma unroll
        for (int i = 0; i < 2; i++) {
            const int g = rt * 64 + (ty << 1) + i;
            const int b = g >> 9, t = g & 511;
            float4 v = make_float4(acc[i][0] + b4.x, acc[i][1] + b4.y,
                                   acc[i][2] + b4.z, acc[i][3] + b4.w);
            v = act4(v, id4, mx4);
            __stcg((float4*)&g_actin[(size_t)(t * BB + b) * XD + col0], v);
        }
    }
    gsync(mygen);

    // ================= Phase B: P = actin @ Wh1a^T + bh1 ===================
    for (int task = bid; task < 512 * 16; task += NB) {
        const int rt = task >> 4, nt = task & 15;
        float acc[2][4];
        gemm_task(g_actin + (size_t)rt * 64 * XD, XD,
                  Wh1 + (size_t)(nt << 6) * (2 * XD), 2 * XD, 8, acc, as2, ws, tx, ty);
        const int col0 = (nt << 6) + (tx << 2);
        const float4 b4 = __ldg((const float4*)&bh1[col0]);
#pragma unroll
        for (int i = 0; i < 2; i++) {
            const int row = rt * 64 + (ty << 1) + i;
            float4 v = make_float4(acc[i][0] + b4.x, acc[i][1] + b4.y,
                                   acc[i][2] + b4.z, acc[i][3] + b4.w);
            __stcg((float4*)&g_P[(size_t)row * XD + col0], v);
        }
    }
    gsync(mygen);

    // ================= preload persistent loop weights into shared =========
    const int nt = bid >> 3;           // output tile 0..15
    const int sp = bid & 7;            // k-split 0..7
    const int n0 = nt << 6;
    const int k0 = sp << 7;
    const int col0 = n0 + (tx << 2);

    stageB_T(Wh1 + (size_t)n0 * (2 * XD) + XD + k0, 2 * XD, ws + 0 * WS_PHASE);
    stageB_T(Wh2 + (size_t)n0 * XD + k0,            XD,     ws + 1 * WS_PHASE);
    stageB_T(Wh3 + (size_t)n0 * XD + k0,            XD,     ws + 2 * WS_PHASE);
    stageB_T(Wr  + (size_t)n0 * XD + k0,            XD,     ws + 3 * WS_PHASE);
    __syncthreads();

    // h-cnt addresses this block polls / publishes
    const unsigned* w1a = &g_hcnt[(3 * 16 + 2 * sp) * 8];     // rs tiles
    const unsigned* w1b = &g_hcnt[(3 * 16 + 2 * sp + 1) * 8];
    const unsigned* w2a = &g_hcnt[(0 * 16 + 2 * sp) * 8];     // h1 tiles
    const unsigned* w2b = &g_hcnt[(0 * 16 + 2 * sp + 1) * 8];
    const unsigned* w3a = &g_hcnt[(1 * 16 + 2 * sp) * 8];     // h2 tiles
    const unsigned* w3b = &g_hcnt[(1 * 16 + 2 * sp + 1) * 8];
    const unsigned* w4a = &g_hcnt[(2 * 16 + 2 * sp) * 8];     // h3 tiles
    const unsigned* w4b = &g_hcnt[(2 * 16 + 2 * sp + 1) * 8];

    // ================= time loop (fence-free dataflow) =====================
    for (int s = 0; s < TT; s++) {
        const unsigned e = (unsigned)(s + 1);

        // ---- Phase 1: h1 = act( (rs@Wh1b^T)*rinv + P[s] ) ----
        waitcnt(w1a, w1b, (unsigned)s);
        {
            stageA_dup(g_rs + k0, XD, as2);
            __syncthreads();
            ull c00 = 0, c01 = 0, c10 = 0, c11 = 0;
            gemm_sh(as2, ws + 0 * WS_PHASE, c00, c01, c10, c11, tx, ty);
            float acc[2][4];
            unpack_acc(c00, c01, c10, c11, acc);
            if (ksplit(0 * 16 + nt, sp, e, acc, tx, ty)) {
                const int4   id4 = __ldg((const int4*)&idx_h1[col0]);
                const float4 mx4 = __ldg((const float4*)&max_h1[col0]);
                const float* Pt = g_P + (size_t)s * BB * XD;
#pragma unroll
                for (int i = 0; i < 2; i++) {
                    const int row = (ty << 1) + i;
                    float4 n0v = __ldcg((const float4*)&g_normpart[row][0]);
                    float4 n1v = __ldcg((const float4*)&g_normpart[row][4]);
                    float4 n2v = __ldcg((const float4*)&g_normpart[row][8]);
                    float4 n3v = __ldcg((const float4*)&g_normpart[row][12]);
                    float ss = ((n0v.x + n0v.y) + (n0v.z + n0v.w))
                             + ((n1v.x + n1v.y) + (n1v.z + n1v.w))
                             + ((n2v.x + n2v.y) + (n2v.z + n2v.w))
                             + ((n3v.x + n3v.y) + (n3v.z + n3v.w));
                    const float rinv = 1.0f / fmaxf(sqrtf(ss), 1e-12f);
                    const float4 p4 = __ldg((const float4*)&Pt[(size_t)row * XD + col0]);
                    float4 v = make_float4(acc[i][0] * rinv + p4.x, acc[i][1] * rinv + p4.y,
                                           acc[i][2] * rinv + p4.z, acc[i][3] * rinv + p4.w);
                    v = act4(v, id4, mx4);
                    __stcg((float4*)&g_h1[row * XD + col0], v);
                }
                publish_h(&g_hcnt[(0 * 16 + nt) * 8]);
            }
        }

        // ---- Phase 2: h2 = act(h1 @ Wh2^T + bh2) ----
        waitcnt(w2a, w2b, e);
        {
            stageA_dup(g_h1 + k0, XD, as2);
            __syncthreads();
            ull c00 = 0, c01 = 0, c10 = 0, c11 = 0;
            gemm_sh(as2, ws + 1 * WS_PHASE, c00, c01, c10, c11, tx, ty);
            float acc[2][4];
            unpack_acc(c00, c01, c10, c11, acc);
            if (ksplit(1 * 16 + nt, sp, e, acc, tx, ty)) {
                const int4   id4 = __ldg((const int4*)&idx_h2[col0]);
                const float4 mx4 = __ldg((const float4*)&max_h2[col0]);
                const float4 b4  = __ldg((const float4*)&bh2[col0]);
#pragma unroll
                for (int i = 0; i < 2; i++) {
                    const int row = (ty << 1) + i;
                    float4 v = make_float4(acc[i][0] + b4.x, acc[i][1] + b4.y,
                                           acc[i][2] + b4.z, acc[i][3] + b4.w);
                    v = act4(v, id4, mx4);
                    __stcg((float4*)&g_h2[row * XD + col0], v);
                }
                publish_h(&g_hcnt[(1 * 16 + nt) * 8]);
            }
        }

        // ---- Phase 3: h3all[s] = act(h2 @ Wh3^T + bh3) ----
        waitcnt(w3a, w3b, e);
        {
            stageA_dup(g_h2 + k0, XD, as2);
            __syncthreads();
            ull c00 = 0, c01 = 0, c10 = 0, c11 = 0;
            gemm_sh(as2, ws + 2 * WS_PHASE, c00, c01, c10, c11, tx, ty);
            float acc[2][4];
            unpack_acc(c00, c01, c10, c11, acc);
            if (ksplit(2 * 16 + nt, sp, e, acc, tx, ty)) {
                const int4   id4 = __ldg((const int4*)&idx_h3[col0]);
                const float4 mx4 = __ldg((const float4*)&max_h3[col0]);
                const float4 b4  = __ldg((const float4*)&bh3[col0]);
                float* h3t = g_h3all + (size_t)s * BB * XD;
#pragma unroll
                for (int i = 0; i < 2; i++) {
                    const int row = (ty << 1) + i;
                    float4 v = make_float4(acc[i][0] + b4.x, acc[i][1] + b4.y,
                                           acc[i][2] + b4.z, acc[i][3] + b4.w);
                    v = act4(v, id4, mx4);
                    __stcg((float4*)&h3t[row * XD + col0], v);
                }
                publish_h(&g_hcnt[(2 * 16 + nt) * 8]);
            }
        }

        // ---- Phase 4: rs = act(h3 @ Wr^T + br) + norm partials ----
        waitcnt(w4a, w4b, e);
        {
            stageA_dup(g_h3all + (size_t)s * BB * XD + k0, XD, as2);
            __syncthreads();
            ull c00 = 0, c01 = 0, c10 = 0, c11 = 0;
            gemm_sh(as2, ws + 3 * WS_PHASE, c00, c01, c10, c11, tx, ty);
            float acc[2][4];
            unpack_acc(c00, c01, c10, c11, acc);
            if (ksplit(3 * 16 + nt, sp, e, acc, tx, ty)) {
                const int4   id4 = __ldg((const int4*)&idx_rec[col0]);
                const float4 mx4 = __ldg((const float4*)&max_rec[col0]);
                const float4 b4  = __ldg((const float4*)&br[col0]);
#pragma unroll
                for (int i = 0; i < 2; i++) {
                    const int row = (ty << 1) + i;
                    float4 v = make_float4(acc[i][0] + b4.x, acc[i][1] + b4.y,
                                           acc[i][2] + b4.z, acc[i][3] + b4.w);
                    v = act4(v, id4, mx4);
                    __stcg((float4*)&g_rs[row * XD + col0], v);
                    float sq = v.x * v.x + v.y * v.y + v.z * v.z + v.w * v.w;
                    sq += __shfl_xor_sync(0xffffffffu, sq, 1, 16);
                    sq += __shfl_xor_sync(0xffffffffu, sq, 2, 16);
                    sq += __shfl_xor_sync(0xffffffffu, sq, 4, 16);
                    sq += __shfl_xor_sync(0xffffffffu, sq, 8, 16);
                    if (tx == 0) __stcg(&g_normpart[row][nt], sq);
                }
                publish_h(&g_hcnt[(3 * 16 + nt) * 8]);
            }
        }
    }
    gsync(mygen);

    // ================= Output GEMM: y = act(H3 @ Wo^T + bo) ================
    for (int task = bid; task < 512 * 4; task += NB) {
        const int t = task >> 2, ot = task & 3;
        float acc[2][4];
        gemm_task(g_h3all + (size_t)t * BB * XD, XD,
                  Wo + (size_t)(ot << 6) * XD, XD, 8, acc, as2, ws, tx, ty);
        const int oc0 = (ot << 6) + (tx << 2);
        const int4   id4 = __ldg((const int4*)&idx_out[oc0]);
        const float4 mx4 = __ldg((const float4*)&max_out[oc0]);
        const float4 b4  = __ldg((const float4*)&bo[oc0]);
#pragma unroll
        for (int i = 0; i < 2; i++) {
            const int b = (ty << 1) + i;   // batch row
            float4 v = make_float4(acc[i][0] + b4.x, acc[i][1] + b4.y,
                                   acc[i][2] + b4.z, acc[i][3] + b4.w);
            v = act4(v, id4, mx4);
            __stcg((float4*)&out[((size_t)b * TT + t) * OUTD + oc0], v);
        }
    }
}

// ------------------------- launch ------------------------------------------
extern "C" void kernel_launch(void* const* d_in, const int* in_sizes, int n_in,
                              void* d_out, int out_size) {
    const float* x       = (const float*)d_in[0];
    const float* Wi      = (const float*)d_in[1];
    const float* bi      = (const float*)d_in[2];
    const float* Wh1     = (const float*)d_in[3];
    const float* bh1     = (const float*)d_in[4];
    const float* Wh2     = (const float*)d_in[5];
    const float* bh2     = (const float*)d_in[6];
    const float* Wh3     = (const float*)d_in[7];
    const float* bh3     = (const float*)d_in[8];
    const float* Wo      = (const float*)d_in[9];
    const float* bo      = (const float*)d_in[10];
    const float* Wr      = (const float*)d_in[11];
    const float* br      = (const float*)d_in[12];
    const float* max_in  = (const float*)d_in[13];
    const float* max_h1  = (const float*)d_in[14];
    const float* max_h2  = (const float*)d_in[15];
    const float* max_h3  = (const float*)d_in[16];
    const float* max_out = (const float*)d_in[17];
    const float* max_rec = (const float*)d_in[18];
    const int*   idx_in  = (const int*)d_in[19];
    const int*   idx_h1  = (const int*)d_in[20];
    const int*   idx_h2  = (const int*)d_in[21];
    const int*   idx_h3  = (const int*)d_in[22];
    const int*   idx_out = (const int*)d_in[23];
    const int*   idx_rec = (const int*)d_in[24];

    static int configured = 0;
    if (!configured) {
        cudaFuncSetAttribute(bnn_kernel, cudaFuncAttributeMaxDynamicSharedMemorySize,
                             SMEM_BYTES);
        configured = 1;
    }

    bnn_kernel<<<NB, NTH, SMEM_BYTES>>>(x, Wi, bi, Wh1, bh1, Wh2, bh2, Wh3, bh3,
                                        Wo, bo, Wr, br,
                                        max_in, max_h1, max_h2, max_h3, max_out, max_rec,
                                        idx_in, idx_h1, idx_h2, idx_h3, idx_out, idx_rec,
                                        (float*)d_out);
}